// round 5
// baseline (speedup 1.0000x reference)
#include <cuda_runtime.h>
#include <cuda_fp16.h>
#include <cstdint>
#include <cstddef>

// ============================================================
// Problem constants
// ============================================================
#define N_TOK 8192
#define OUT_F 4096
#define IN_F  4096
#define NBITS 8
#define STEPF 0.0078125f

// GEMM tiling: 3 CTAs/SM
#define BM 128
#define BN 64
#define BK 64
#define KTILES (IN_F / BK)      // 64
#define NSTAGES 3
#define GTHREADS 256

// SMEM stage: A 128x64 f16 (128B rows) = 16KB, B 64x64 f16 = 8KB
#define A_STAGE_BYTES 16384
#define STAGE_BYTES   24576
#define SMEM_TOTAL    (NSTAGES * STAGE_BYTES)   // 73728

// ============================================================
// Device scratch (allocation-free rule: __device__ globals)
// ============================================================
__device__ __align__(16) __half g_X[(size_t)N_TOK * IN_F];   // 64 MB
__device__ __align__(16) __half g_W[(size_t)OUT_F * IN_F];   // 32 MB

// ============================================================
// Helpers
// ============================================================
__device__ __forceinline__ uint32_t smem_u32(const void* p) {
    uint32_t a;
    asm("{ .reg .u64 t; cvta.to.shared.u64 t, %1; cvt.u32.u64 %0, t; }"
        : "=r"(a) : "l"(p));
    return a;
}

__device__ __forceinline__ void cp_async16(uint32_t saddr, const void* gaddr) {
    asm volatile("cp.async.cg.shared.global [%0], [%1], 16;"
                 :: "r"(saddr), "l"(gaddr));
}

__device__ __forceinline__ void ldmatrix_x4(uint32_t& r0, uint32_t& r1,
                                            uint32_t& r2, uint32_t& r3,
                                            uint32_t addr) {
    asm volatile("ldmatrix.sync.aligned.m8n8.x4.shared.b16 {%0,%1,%2,%3}, [%4];"
                 : "=r"(r0), "=r"(r1), "=r"(r2), "=r"(r3) : "r"(addr));
}

__device__ __forceinline__ void mma_16816(float& d0, float& d1, float& d2, float& d3,
                                          uint32_t a0, uint32_t a1, uint32_t a2, uint32_t a3,
                                          uint32_t b0, uint32_t b1) {
    asm volatile(
        "mma.sync.aligned.m16n8k16.row.col.f32.f16.f16.f32 "
        "{%0,%1,%2,%3}, {%4,%5,%6,%7}, {%8,%9}, {%0,%1,%2,%3};"
        : "+f"(d0), "+f"(d1), "+f"(d2), "+f"(d3)
        : "r"(a0), "r"(a1), "r"(a2), "r"(a3), "r"(b0), "r"(b1));
}

// ============================================================
// Fused prep kernel: blocks [0, WBLOCKS) build W, rest convert X.
// ============================================================
#define WBLOCKS 32768   // (OUT_F*IN_F/2) / 256
#define XBLOCKS 32768   // (N_TOK*IN_F/4) / 256

__global__ void prep_kernel(const float* __restrict__ x,
                            const float* __restrict__ w_twos,
                            const float* __restrict__ base) {
    if (blockIdx.x < WBLOCKS) {
        size_t p = (size_t)blockIdx.x * blockDim.x + threadIdx.x;

        float bs[NBITS];
#pragma unroll
        for (int j = 0; j < NBITS; j++) bs[j] = __ldg(base + j);

        const float4* src = reinterpret_cast<const float4*>(w_twos + p * 2 * NBITS);
        float4 a0 = src[0], a1 = src[1], a2 = src[2], a3 = src[3];

        float w0 = a0.x * bs[0] + a0.y * bs[1] + a0.z * bs[2] + a0.w * bs[3] +
                   a1.x * bs[4] + a1.y * bs[5] + a1.z * bs[6] + a1.w * bs[7];
        float w1 = a2.x * bs[0] + a2.y * bs[1] + a2.z * bs[2] + a2.w * bs[3] +
                   a3.x * bs[4] + a3.y * bs[5] + a3.z * bs[6] + a3.w * bs[7];

        __half2 h = __floats2half2_rn(w0 * STEPF, w1 * STEPF);
        reinterpret_cast<uint32_t*>(g_W)[p] = *reinterpret_cast<uint32_t*>(&h);
    } else {
        size_t i = (size_t)(blockIdx.x - WBLOCKS) * blockDim.x + threadIdx.x;
        float4 v = reinterpret_cast<const float4*>(x)[i];
        __half2 h01 = __floats2half2_rn(v.x, v.y);
        __half2 h23 = __floats2half2_rn(v.z, v.w);
        uint2 pk;
        pk.x = *reinterpret_cast<uint32_t*>(&h01);
        pk.y = *reinterpret_cast<uint32_t*>(&h23);
        reinterpret_cast<uint2*>(g_X)[i] = pk;
    }
}

// ============================================================
// fp16 mma.sync GEMM  out[m,n] = sum_k X[m,k]*W[n,k] + b[n]
// BM=128, BN=64, BK=64, 8 warps (4m x 2n), warp tile 32x32,
// 3-stage cp.async pipeline, 3 CTAs per SM.
// ============================================================
__global__ __launch_bounds__(GTHREADS, 3)
void gemm_kernel(const float* __restrict__ bias, float* __restrict__ out) {
    extern __shared__ char sm[];
    const uint32_t smem_base = smem_u32(sm);
    const int tid  = threadIdx.x;
    const int wid  = tid >> 5;
    const int lane = tid & 31;
    const int warp_m = wid >> 1;   // 0..3, 32 rows each
    const int warp_n = wid & 1;    // 0..1, 32 cols each
    const int m0 = blockIdx.y * BM;
    const int n0 = blockIdx.x * BN;

    // ---- per-lane ldmatrix addressing ----
    // A frags (x4): row = warp_m*32 + im*16 + (lane&15), k-half = lane>>4
    uint32_t a_row[2], a_xor[2];
#pragma unroll
    for (int im = 0; im < 2; ++im) {
        int r = warp_m * 32 + im * 16 + (lane & 15);
        a_row[im] = (uint32_t)(r * 128);
        a_xor[im] = (uint32_t)((r & 7) * 16);
    }
    const uint32_t a_khb = (uint32_t)((lane >> 4) * 16);

    // B frag pairs (x4): pair jp covers n-frags 2jp,2jp+1.
    uint32_t b_row[2], b_xor[2];
#pragma unroll
    for (int jp = 0; jp < 2; ++jp) {
        int r = warp_n * 32 + jp * 16 + ((lane >> 4) * 8) + (lane & 7);
        b_row[jp] = (uint32_t)(A_STAGE_BYTES + r * 128);
        b_xor[jp] = (uint32_t)((r & 7) * 16);
    }
    const uint32_t b_khb = (uint32_t)(((lane >> 3) & 1) * 16);

    // ---- cp.async lane assignments: A 1024 chunks (4/thr), B 512 (2/thr) ----
    uint32_t a_soff[4];  const __half* a_gp[4];
    uint32_t b_soff[2];  const __half* b_gp[2];
#pragma unroll
    for (int i = 0; i < 4; ++i) {
        int id = tid + i * 256;
        int r = id >> 3, c = id & 7;
        a_soff[i] = (uint32_t)(r * 128 + ((c * 16) ^ ((r & 7) * 16)));
        a_gp[i] = g_X + (size_t)(m0 + r) * IN_F + c * 8;
    }
#pragma unroll
    for (int i = 0; i < 2; ++i) {
        int id = tid + i * 256;
        int r = id >> 3, c = id & 7;
        b_soff[i] = (uint32_t)(A_STAGE_BYTES + r * 128 + ((c * 16) ^ ((r & 7) * 16)));
        b_gp[i] = g_W + (size_t)(n0 + r) * IN_F + c * 8;
    }

    float acc[2][4][4];
#pragma unroll
    for (int im = 0; im < 2; ++im)
#pragma unroll
        for (int jn = 0; jn < 4; ++jn)
#pragma unroll
            for (int q = 0; q < 4; ++q) acc[im][jn][q] = 0.0f;

    // ---- prologue ----
#pragma unroll
    for (int s = 0; s < NSTAGES - 1; ++s) {
        uint32_t sb = smem_base + s * STAGE_BYTES;
        int kof = s * BK;
#pragma unroll
        for (int i = 0; i < 4; ++i) cp_async16(sb + a_soff[i], a_gp[i] + kof);
#pragma unroll
        for (int i = 0; i < 2; ++i) cp_async16(sb + b_soff[i], b_gp[i] + kof);
        asm volatile("cp.async.commit_group;");
    }

    // ---- main loop ----
    int ld_stage = NSTAGES - 1;
    int cp_stage = 0;

    for (int kt = 0; kt < KTILES; ++kt) {
        asm volatile("cp.async.wait_group %0;" :: "n"(NSTAGES - 2));
        __syncthreads();

        int ktn = kt + NSTAGES - 1;
        if (ktn < KTILES) {
            uint32_t sb = smem_base + ld_stage * STAGE_BYTES;
            int kof = ktn * BK;
#pragma unroll
            for (int i = 0; i < 4; ++i) cp_async16(sb + a_soff[i], a_gp[i] + kof);
#pragma unroll
            for (int i = 0; i < 2; ++i) cp_async16(sb + b_soff[i], b_gp[i] + kof);
        }
        asm volatile("cp.async.commit_group;");

        uint32_t sS = smem_base + cp_stage * STAGE_BYTES;

#pragma unroll
        for (int ks = 0; ks < 4; ++ks) {
            uint32_t k32 = (uint32_t)(ks * 32);

            uint32_t a[2][4];
#pragma unroll
            for (int im = 0; im < 2; ++im) {
                uint32_t addr = sS + a_row[im] + ((k32 + a_khb) ^ a_xor[im]);
                ldmatrix_x4(a[im][0], a[im][1], a[im][2], a[im][3], addr);
            }
            uint32_t b[4][2];
#pragma unroll
            for (int jp = 0; jp < 2; ++jp) {
                uint32_t addr = sS + b_row[jp] + ((k32 + b_khb) ^ b_xor[jp]);
                ldmatrix_x4(b[2 * jp][0], b[2 * jp][1],
                            b[2 * jp + 1][0], b[2 * jp + 1][1], addr);
            }
#pragma unroll
            for (int im = 0; im < 2; ++im)
#pragma unroll
                for (int jn = 0; jn < 4; ++jn)
                    mma_16816(acc[im][jn][0], acc[im][jn][1],
                              acc[im][jn][2], acc[im][jn][3],
                              a[im][0], a[im][1], a[im][2], a[im][3],
                              b[jn][0], b[jn][1]);
        }

        ld_stage = (ld_stage == NSTAGES - 1) ? 0 : ld_stage + 1;
        cp_stage = (cp_stage == NSTAGES - 1) ? 0 : cp_stage + 1;
    }

    // ---- epilogue: bias + store ----
#pragma unroll
    for (int im = 0; im < 2; ++im) {
        int r0 = m0 + warp_m * 32 + im * 16 + (lane >> 2);
        int r1 = r0 + 8;
#pragma unroll
        for (int jn = 0; jn < 4; ++jn) {
            int c = n0 + warp_n * 32 + jn * 8 + (lane & 3) * 2;
            float2 bv = *reinterpret_cast<const float2*>(bias + c);
            float2 o0, o1;
            o0.x = acc[im][jn][0] + bv.x;
            o0.y = acc[im][jn][1] + bv.y;
            o1.x = acc[im][jn][2] + bv.x;
            o1.y = acc[im][jn][3] + bv.y;
            *reinterpret_cast<float2*>(out + (size_t)r0 * OUT_F + c) = o0;
            *reinterpret_cast<float2*>(out + (size_t)r1 * OUT_F + c) = o1;
        }
    }
}

// ============================================================
// Host launcher
// ============================================================
extern "C" void kernel_launch(void* const* d_in, const int* in_sizes, int n_in,
                              void* d_out, int out_size) {
    const float* x      = (const float*)d_in[0];
    const float* w_twos = (const float*)d_in[1];
    const float* b      = (const float*)d_in[2];
    const float* base   = (const float*)d_in[3];
    float* out = (float*)d_out;

    cudaFuncSetAttribute(gemm_kernel,
                         cudaFuncAttributeMaxDynamicSharedMemorySize, SMEM_TOTAL);

    prep_kernel<<<WBLOCKS + XBLOCKS, 256>>>(x, w_twos, base);

    dim3 grid(OUT_F / BN, N_TOK / BM);
    gemm_kernel<<<grid, GTHREADS, SMEM_TOTAL>>>(b, out);
}

// round 8
// speedup vs baseline: 1.0836x; 1.0836x over previous
#include <cuda_runtime.h>
#include <cuda_fp16.h>
#include <cstdint>
#include <cstddef>

// ============================================================
// Problem constants
// ============================================================
#define N_TOK 8192
#define OUT_F 4096
#define IN_F  4096
#define NBITS 8
#define STEPF 0.0078125f

// GEMM tiling: 2 CTAs/SM (R4 config, restructured loop)
#define BM 128
#define BN 128
#define BK 64
#define KTILES (IN_F / BK)      // 64
#define NSTAGES 3
#define GTHREADS 256

// SMEM stage: A 128x64 f16 (128B rows) = 16KB, B 128x64 f16 = 16KB
#define A_STAGE_BYTES 16384
#define STAGE_BYTES   32768
#define SMEM_TOTAL    (NSTAGES * STAGE_BYTES)   // 98304

// ============================================================
// Device scratch (allocation-free rule: __device__ globals)
// ============================================================
__device__ __align__(16) __half g_X[(size_t)N_TOK * IN_F];   // 64 MB
__device__ __align__(16) __half g_W[(size_t)OUT_F * IN_F];   // 32 MB

// ============================================================
// Helpers
// ============================================================
__device__ __forceinline__ uint32_t smem_u32(const void* p) {
    uint32_t a;
    asm("{ .reg .u64 t; cvta.to.shared.u64 t, %1; cvt.u32.u64 %0, t; }"
        : "=r"(a) : "l"(p));
    return a;
}

__device__ __forceinline__ void cp_async16(uint32_t saddr, const void* gaddr) {
    asm volatile("cp.async.cg.shared.global [%0], [%1], 16;"
                 :: "r"(saddr), "l"(gaddr));
}

__device__ __forceinline__ void ldmatrix_x4(uint32_t& r0, uint32_t& r1,
                                            uint32_t& r2, uint32_t& r3,
                                            uint32_t addr) {
    asm volatile("ldmatrix.sync.aligned.m8n8.x4.shared.b16 {%0,%1,%2,%3}, [%4];"
                 : "=r"(r0), "=r"(r1), "=r"(r2), "=r"(r3) : "r"(addr));
}

__device__ __forceinline__ void mma_16816(float& d0, float& d1, float& d2, float& d3,
                                          uint32_t a0, uint32_t a1, uint32_t a2, uint32_t a3,
                                          uint32_t b0, uint32_t b1) {
    asm volatile(
        "mma.sync.aligned.m16n8k16.row.col.f32.f16.f16.f32 "
        "{%0,%1,%2,%3}, {%4,%5,%6,%7}, {%8,%9}, {%0,%1,%2,%3};"
        : "+f"(d0), "+f"(d1), "+f"(d2), "+f"(d3)
        : "r"(a0), "r"(a1), "r"(a2), "r"(a3), "r"(b0), "r"(b1));
}

// ============================================================
// Fused prep kernel: blocks [0, WBLOCKS) build W, rest convert X.
// ============================================================
#define WBLOCKS 32768   // (OUT_F*IN_F/2) / 256
#define XBLOCKS 32768   // (N_TOK*IN_F/4) / 256

__global__ void prep_kernel(const float* __restrict__ x,
                            const float* __restrict__ w_twos,
                            const float* __restrict__ base) {
    if (blockIdx.x < WBLOCKS) {
        size_t p = (size_t)blockIdx.x * blockDim.x + threadIdx.x;

        float bs[NBITS];
#pragma unroll
        for (int j = 0; j < NBITS; j++) bs[j] = __ldg(base + j);

        const float4* src = reinterpret_cast<const float4*>(w_twos + p * 2 * NBITS);
        float4 a0 = src[0], a1 = src[1], a2 = src[2], a3 = src[3];

        float w0 = a0.x * bs[0] + a0.y * bs[1] + a0.z * bs[2] + a0.w * bs[3] +
                   a1.x * bs[4] + a1.y * bs[5] + a1.z * bs[6] + a1.w * bs[7];
        float w1 = a2.x * bs[0] + a2.y * bs[1] + a2.z * bs[2] + a2.w * bs[3] +
                   a3.x * bs[4] + a3.y * bs[5] + a3.z * bs[6] + a3.w * bs[7];

        __half2 h = __floats2half2_rn(w0 * STEPF, w1 * STEPF);
        reinterpret_cast<uint32_t*>(g_W)[p] = *reinterpret_cast<uint32_t*>(&h);
    } else {
        size_t i = (size_t)(blockIdx.x - WBLOCKS) * blockDim.x + threadIdx.x;
        float4 v = reinterpret_cast<const float4*>(x)[i];
        __half2 h01 = __floats2half2_rn(v.x, v.y);
        __half2 h23 = __floats2half2_rn(v.z, v.w);
        uint2 pk;
        pk.x = *reinterpret_cast<uint32_t*>(&h01);
        pk.y = *reinterpret_cast<uint32_t*>(&h23);
        reinterpret_cast<uint2*>(g_X)[i] = pk;
    }
}

// ============================================================
// fp16 mma.sync GEMM  out[m,n] = sum_k X[m,k]*W[n,k] + b[n]
// BM=128, BN=128, BK=64, 8 warps (2m x 4n, warp tile 64x32),
// 3-stage cp.async pipeline, 2 CTAs/SM, tail-barrier loop with
// cross-tile ks0 fragment prefetch.
// ============================================================
__global__ __launch_bounds__(GTHREADS, 2)
void gemm_kernel(const float* __restrict__ bias, float* __restrict__ out) {
    extern __shared__ char sm[];
    const uint32_t smem_base = smem_u32(sm);
    const int tid  = threadIdx.x;
    const int wid  = tid >> 5;
    const int lane = tid & 31;
    const int warp_m = wid & 1;    // 64 rows each
    const int warp_n = wid >> 1;   // 32 cols each
    const int m0 = blockIdx.y * BM;
    const int n0 = blockIdx.x * BN;

    // ---- per-lane ldmatrix addressing ----
    uint32_t a_row[4], a_xor[4];
#pragma unroll
    for (int im = 0; im < 4; ++im) {
        int r = warp_m * 64 + im * 16 + (lane & 15);
        a_row[im] = (uint32_t)(r * 128);
        a_xor[im] = (uint32_t)((r & 7) * 16);
    }
    const uint32_t a_khb = (uint32_t)((lane >> 4) * 16);

    uint32_t b_row[2], b_xor[2];
#pragma unroll
    for (int jp = 0; jp < 2; ++jp) {
        int r = warp_n * 32 + jp * 16 + ((lane >> 4) * 8) + (lane & 7);
        b_row[jp] = (uint32_t)(A_STAGE_BYTES + r * 128);
        b_xor[jp] = (uint32_t)((r & 7) * 16);
    }
    const uint32_t b_khb = (uint32_t)(((lane >> 3) & 1) * 16);

    // ---- cp.async lane assignments: A 1024 chunks, B 1024 chunks; 4 each ----
    uint32_t a_soff[4];  const __half* a_gp[4];
    uint32_t b_soff[4];  const __half* b_gp[4];
#pragma unroll
    for (int i = 0; i < 4; ++i) {
        int id = tid + i * 256;
        int r = id >> 3, c = id & 7;
        uint32_t so = (uint32_t)(r * 128 + ((c * 16) ^ ((r & 7) * 16)));
        a_soff[i] = so;
        b_soff[i] = so + A_STAGE_BYTES;
        a_gp[i] = g_X + (size_t)(m0 + r) * IN_F + c * 8;
        b_gp[i] = g_W + (size_t)(n0 + r) * IN_F + c * 8;
    }

    float acc[4][4][4];
#pragma unroll
    for (int im = 0; im < 4; ++im)
#pragma unroll
        for (int jn = 0; jn < 4; ++jn)
#pragma unroll
            for (int q = 0; q < 4; ++q) acc[im][jn][q] = 0.0f;

    // ---- prologue: fill stages 0,1 (tiles 0,1) ----
#pragma unroll
    for (int s = 0; s < NSTAGES - 1; ++s) {
        uint32_t sb = smem_base + s * STAGE_BYTES;
        int kof = s * BK;
#pragma unroll
        for (int i = 0; i < 4; ++i) cp_async16(sb + a_soff[i], a_gp[i] + kof);
#pragma unroll
        for (int i = 0; i < 4; ++i) cp_async16(sb + b_soff[i], b_gp[i] + kof);
        asm volatile("cp.async.commit_group;");
    }

    // wait for tile 0 (1 group may stay outstanding), publish, prefetch ks0
    asm volatile("cp.async.wait_group %0;" :: "n"(NSTAGES - 2));
    __syncthreads();

    uint32_t a[4][4];   // single-buffer fragments
    uint32_t b[4][2];

    {
        uint32_t sS = smem_base;  // stage 0
#pragma unroll
        for (int im = 0; im < 4; ++im)
            ldmatrix_x4(a[im][0], a[im][1], a[im][2], a[im][3],
                        sS + a_row[im] + (a_khb ^ a_xor[im]));
#pragma unroll
        for (int jp = 0; jp < 2; ++jp)
            ldmatrix_x4(b[2 * jp][0], b[2 * jp][1],
                        b[2 * jp + 1][0], b[2 * jp + 1][1],
                        sS + b_row[jp] + (b_khb ^ b_xor[jp]));
    }

    // ---- main loop: barrier at tail, ks0 frags prefetched across it ----
    int cp_stage = 0;            // stage holding tile kt
    int ld_stage = NSTAGES - 1;  // stage to fill with tile kt+2

    for (int kt = 0; kt < KTILES; ++kt) {
        uint32_t sS = smem_base + cp_stage * STAGE_BYTES;

        // ks0 MMAs first — tensor pipe restarts immediately after barrier
#pragma unroll
        for (int im = 0; im < 4; ++im)
#pragma unroll
            for (int jn = 0; jn < 4; ++jn)
                mma_16816(acc[im][jn][0], acc[im][jn][1],
                          acc[im][jn][2], acc[im][jn][3],
                          a[im][0], a[im][1], a[im][2], a[im][3],
                          b[jn][0], b[jn][1]);

        // issue next-stage copies under the tensor work
        int ktn = kt + NSTAGES - 1;
        if (ktn < KTILES) {
            uint32_t sb = smem_base + ld_stage * STAGE_BYTES;
            int kof = ktn * BK;
#pragma unroll
            for (int i = 0; i < 4; ++i) cp_async16(sb + a_soff[i], a_gp[i] + kof);
#pragma unroll
            for (int i = 0; i < 4; ++i) cp_async16(sb + b_soff[i], b_gp[i] + kof);
        }
        asm volatile("cp.async.commit_group;");

        // ks1..ks3: load frags (single buffer; WAR resolved by rbar) + MMA
#pragma unroll
        for (int ks = 1; ks < 4; ++ks) {
            uint32_t k32 = (uint32_t)(ks * 32);
#pragma unroll
            for (int im = 0; im < 4; ++im)
                ldmatrix_x4(a[im][0], a[im][1], a[im][2], a[im][3],
                            sS + a_row[im] + ((k32 + a_khb) ^ a_xor[im]));
#pragma unroll
            for (int jp = 0; jp < 2; ++jp)
                ldmatrix_x4(b[2 * jp][0], b[2 * jp][1],
                            b[2 * jp + 1][0], b[2 * jp + 1][1],
                            sS + b_row[jp] + ((k32 + b_khb) ^ b_xor[jp]));
#pragma unroll
            for (int im = 0; im < 4; ++im)
#pragma unroll
                for (int jn = 0; jn < 4; ++jn)
                    mma_16816(acc[im][jn][0], acc[im][jn][1],
                              acc[im][jn][2], acc[im][jn][3],
                              a[im][0], a[im][1], a[im][2], a[im][3],
                              b[jn][0], b[jn][1]);
        }

        // tail rendezvous: tile kt+1's copies complete (mine), publish all,
        // everyone done reading stage kt -> next iter may overwrite its ring slot
        asm volatile("cp.async.wait_group %0;" :: "n"(NSTAGES - 2));
        __syncthreads();

        // cross-tile prefetch: ks0 frags of tile kt+1 (now safely visible)
        if (kt + 1 < KTILES) {
            int ns = (cp_stage == NSTAGES - 1) ? 0 : cp_stage + 1;
            uint32_t sN = smem_base + ns * STAGE_BYTES;
#pragma unroll
            for (int im = 0; im < 4; ++im)
                ldmatrix_x4(a[im][0], a[im][1], a[im][2], a[im][3],
                            sN + a_row[im] + (a_khb ^ a_xor[im]));
#pragma unroll
            for (int jp = 0; jp < 2; ++jp)
                ldmatrix_x4(b[2 * jp][0], b[2 * jp][1],
                            b[2 * jp + 1][0], b[2 * jp + 1][1],
                            sN + b_row[jp] + (b_khb ^ b_xor[jp]));
        }

        ld_stage = (ld_stage == NSTAGES - 1) ? 0 : ld_stage + 1;
        cp_stage = (cp_stage == NSTAGES - 1) ? 0 : cp_stage + 1;
    }

    // ---- epilogue: bias + store ----
#pragma unroll
    for (int im = 0; im < 4; ++im) {
        int r0 = m0 + warp_m * 64 + im * 16 + (lane >> 2);
        int r1 = r0 + 8;
#pragma unroll
        for (int jn = 0; jn < 4; ++jn) {
            int c = n0 + warp_n * 32 + jn * 8 + (lane & 3) * 2;
            float2 bv = *reinterpret_cast<const float2*>(bias + c);
            float2 o0, o1;
            o0.x = acc[im][jn][0] + bv.x;
            o0.y = acc[im][jn][1] + bv.y;
            o1.x = acc[im][jn][2] + bv.x;
            o1.y = acc[im][jn][3] + bv.y;
            *reinterpret_cast<float2*>(out + (size_t)r0 * OUT_F + c) = o0;
            *reinterpret_cast<float2*>(out + (size_t)r1 * OUT_F + c) = o1;
        }
    }
}

// ============================================================
// Host launcher
// ============================================================
extern "C" void kernel_launch(void* const* d_in, const int* in_sizes, int n_in,
                              void* d_out, int out_size) {
    const float* x      = (const float*)d_in[0];
    const float* w_twos = (const float*)d_in[1];
    const float* b      = (const float*)d_in[2];
    const float* base   = (const float*)d_in[3];
    float* out = (float*)d_out;

    cudaFuncSetAttribute(gemm_kernel,
                         cudaFuncAttributeMaxDynamicSharedMemorySize, SMEM_TOTAL);

    prep_kernel<<<WBLOCKS + XBLOCKS, 256>>>(x, w_twos, base);

    dim3 grid(OUT_F / BN, N_TOK / BM);
    gemm_kernel<<<grid, GTHREADS, SMEM_TOTAL>>>(b, out);
}

// round 9
// speedup vs baseline: 1.1160x; 1.0299x over previous
#include <cuda_runtime.h>
#include <cuda_fp16.h>
#include <cstdint>
#include <cstddef>

// ============================================================
// Problem constants
// ============================================================
#define N_TOK 8192
#define OUT_F 4096
#define IN_F  4096
#define NBITS 8
#define STEPF 0.0078125f

// GEMM tiling: 1 CTA/SM, fat registers, 64x64 warp tile
#define BM 128
#define BN 256
#define BK 64
#define KTILES (IN_F / BK)      // 64
#define NSTAGES 4
#define GTHREADS 256

// SMEM stage: A 128x64 f16 (128B rows) = 16KB, B 256x64 f16 = 32KB
#define A_STAGE_BYTES 16384
#define STAGE_BYTES   49152
#define SMEM_TOTAL    (NSTAGES * STAGE_BYTES)   // 196608

// ============================================================
// Device scratch (allocation-free rule: __device__ globals)
// ============================================================
__device__ __align__(16) __half g_X[(size_t)N_TOK * IN_F];   // 64 MB
__device__ __align__(16) __half g_W[(size_t)OUT_F * IN_F];   // 32 MB

// ============================================================
// Helpers
// ============================================================
__device__ __forceinline__ uint32_t smem_u32(const void* p) {
    uint32_t a;
    asm("{ .reg .u64 t; cvta.to.shared.u64 t, %1; cvt.u32.u64 %0, t; }"
        : "=r"(a) : "l"(p));
    return a;
}

__device__ __forceinline__ void cp_async16(uint32_t saddr, const void* gaddr) {
    asm volatile("cp.async.cg.shared.global [%0], [%1], 16;"
                 :: "r"(saddr), "l"(gaddr));
}

__device__ __forceinline__ void ldmatrix_x4(uint32_t& r0, uint32_t& r1,
                                            uint32_t& r2, uint32_t& r3,
                                            uint32_t addr) {
    asm volatile("ldmatrix.sync.aligned.m8n8.x4.shared.b16 {%0,%1,%2,%3}, [%4];"
                 : "=r"(r0), "=r"(r1), "=r"(r2), "=r"(r3) : "r"(addr));
}

__device__ __forceinline__ void mma_16816(float& d0, float& d1, float& d2, float& d3,
                                          uint32_t a0, uint32_t a1, uint32_t a2, uint32_t a3,
                                          uint32_t b0, uint32_t b1) {
    asm volatile(
        "mma.sync.aligned.m16n8k16.row.col.f32.f16.f16.f32 "
        "{%0,%1,%2,%3}, {%4,%5,%6,%7}, {%8,%9}, {%0,%1,%2,%3};"
        : "+f"(d0), "+f"(d1), "+f"(d2), "+f"(d3)
        : "r"(a0), "r"(a1), "r"(a2), "r"(a3), "r"(b0), "r"(b1));
}

// ============================================================
// Fused prep kernel: blocks [0, WBLOCKS) build W, rest convert X.
// (measured at its HBM roofline — do not touch)
// ============================================================
#define WBLOCKS 32768   // (OUT_F*IN_F/2) / 256
#define XBLOCKS 32768   // (N_TOK*IN_F/4) / 256

__global__ void prep_kernel(const float* __restrict__ x,
                            const float* __restrict__ w_twos,
                            const float* __restrict__ base) {
    if (blockIdx.x < WBLOCKS) {
        size_t p = (size_t)blockIdx.x * blockDim.x + threadIdx.x;

        float bs[NBITS];
#pragma unroll
        for (int j = 0; j < NBITS; j++) bs[j] = __ldg(base + j);

        const float4* src = reinterpret_cast<const float4*>(w_twos + p * 2 * NBITS);
        float4 a0 = src[0], a1 = src[1], a2 = src[2], a3 = src[3];

        float w0 = a0.x * bs[0] + a0.y * bs[1] + a0.z * bs[2] + a0.w * bs[3] +
                   a1.x * bs[4] + a1.y * bs[5] + a1.z * bs[6] + a1.w * bs[7];
        float w1 = a2.x * bs[0] + a2.y * bs[1] + a2.z * bs[2] + a2.w * bs[3] +
                   a3.x * bs[4] + a3.y * bs[5] + a3.z * bs[6] + a3.w * bs[7];

        __half2 h = __floats2half2_rn(w0 * STEPF, w1 * STEPF);
        reinterpret_cast<uint32_t*>(g_W)[p] = *reinterpret_cast<uint32_t*>(&h);
    } else {
        size_t i = (size_t)(blockIdx.x - WBLOCKS) * blockDim.x + threadIdx.x;
        float4 v = reinterpret_cast<const float4*>(x)[i];
        __half2 h01 = __floats2half2_rn(v.x, v.y);
        __half2 h23 = __floats2half2_rn(v.z, v.w);
        uint2 pk;
        pk.x = *reinterpret_cast<uint32_t*>(&h01);
        pk.y = *reinterpret_cast<uint32_t*>(&h23);
        reinterpret_cast<uint2*>(g_X)[i] = pk;
    }
}

// ============================================================
// fp16 mma.sync GEMM  out[m,n] = sum_k X[m,k]*W[n,k] + b[n]
// BM=128, BN=256, BK=64, 8 warps (2m x 4n, warp tile 64x64),
// 4-stage cp.async ring, 1 CTA/SM, tail-barrier loop with
// cross-tile ks0 fragment prefetch. 128 B LDSM / MMA.
// ============================================================
__global__ __launch_bounds__(GTHREADS, 1)
void gemm_kernel(const float* __restrict__ bias, float* __restrict__ out) {
    extern __shared__ char sm[];
    const uint32_t smem_base = smem_u32(sm);
    const int tid  = threadIdx.x;
    const int wid  = tid >> 5;
    const int lane = tid & 31;
    const int warp_m = wid & 1;    // 64 rows each
    const int warp_n = wid >> 1;   // 0..3, 64 cols each
    const int m0 = blockIdx.y * BM;
    const int n0 = blockIdx.x * BN;

    // ---- per-lane ldmatrix addressing ----
    // A frags: 4 m-frags of 16 rows; LDSM.x4 covers one m-frag x both k-halves
    uint32_t a_row[4], a_xor[4];
#pragma unroll
    for (int im = 0; im < 4; ++im) {
        int r = warp_m * 64 + im * 16 + (lane & 15);
        a_row[im] = (uint32_t)(r * 128);
        a_xor[im] = (uint32_t)((r & 7) * 16);
    }
    const uint32_t a_khb = (uint32_t)((lane >> 4) * 16);

    // B frag pairs: 8 n-frags as 4 pairs; LDSM.x4 covers 2 n-frags x 2 k-halves
    uint32_t b_row[4], b_xor[4];
#pragma unroll
    for (int jp = 0; jp < 4; ++jp) {
        int r = warp_n * 64 + jp * 16 + ((lane >> 4) * 8) + (lane & 7);
        b_row[jp] = (uint32_t)(A_STAGE_BYTES + r * 128);
        b_xor[jp] = (uint32_t)((r & 7) * 16);
    }
    const uint32_t b_khb = (uint32_t)(((lane >> 3) & 1) * 16);

    // ---- cp.async lane assignments: A 1024 chunks (4/thr), B 2048 (8/thr) ----
    uint32_t a_soff[4];  const __half* a_gp[4];
    uint32_t b_soff[8];  const __half* b_gp[8];
#pragma unroll
    for (int i = 0; i < 4; ++i) {
        int id = tid + i * 256;
        int r = id >> 3, c = id & 7;
        a_soff[i] = (uint32_t)(r * 128 + ((c * 16) ^ ((r & 7) * 16)));
        a_gp[i] = g_X + (size_t)(m0 + r) * IN_F + c * 8;
    }
#pragma unroll
    for (int i = 0; i < 8; ++i) {
        int id = tid + i * 256;
        int r = id >> 3, c = id & 7;
        b_soff[i] = (uint32_t)(A_STAGE_BYTES + r * 128 + ((c * 16) ^ ((r & 7) * 16)));
        b_gp[i] = g_W + (size_t)(n0 + r) * IN_F + c * 8;
    }

    float acc[4][8][4];   // 128 regs: warp tile 64x64
#pragma unroll
    for (int im = 0; im < 4; ++im)
#pragma unroll
        for (int jn = 0; jn < 8; ++jn)
#pragma unroll
            for (int q = 0; q < 4; ++q) acc[im][jn][q] = 0.0f;

    // ---- prologue: fill stages 0..2 (tiles 0..2) ----
#pragma unroll
    for (int s = 0; s < NSTAGES - 1; ++s) {
        uint32_t sb = smem_base + s * STAGE_BYTES;
        int kof = s * BK;
#pragma unroll
        for (int i = 0; i < 4; ++i) cp_async16(sb + a_soff[i], a_gp[i] + kof);
#pragma unroll
        for (int i = 0; i < 8; ++i) cp_async16(sb + b_soff[i], b_gp[i] + kof);
        asm volatile("cp.async.commit_group;");
    }

    // wait for tile 0 (2 groups may stay outstanding), publish, prefetch ks0
    asm volatile("cp.async.wait_group %0;" :: "n"(NSTAGES - 2));
    __syncthreads();

    uint32_t a[4][4];   // single-buffer fragments
    uint32_t b[8][2];

    {
        uint32_t sS = smem_base;  // stage 0
#pragma unroll
        for (int im = 0; im < 4; ++im)
            ldmatrix_x4(a[im][0], a[im][1], a[im][2], a[im][3],
                        sS + a_row[im] + (a_khb ^ a_xor[im]));
#pragma unroll
        for (int jp = 0; jp < 4; ++jp)
            ldmatrix_x4(b[2 * jp][0], b[2 * jp][1],
                        b[2 * jp + 1][0], b[2 * jp + 1][1],
                        sS + b_row[jp] + (b_khb ^ b_xor[jp]));
    }

    // ---- main loop: tail barrier, cross-tile ks0 prefetch ----
    int cp_stage = 0;            // stage holding tile kt
    int ld_stage = NSTAGES - 1;  // stage to fill with tile kt+3

    for (int kt = 0; kt < KTILES; ++kt) {
        uint32_t sS = smem_base + cp_stage * STAGE_BYTES;

        // ks0 MMAs first — tensor pipe restarts immediately after barrier
#pragma unroll
        for (int im = 0; im < 4; ++im)
#pragma unroll
            for (int jn = 0; jn < 8; ++jn)
                mma_16816(acc[im][jn][0], acc[im][jn][1],
                          acc[im][jn][2], acc[im][jn][3],
                          a[im][0], a[im][1], a[im][2], a[im][3],
                          b[jn][0], b[jn][1]);

        // A copies for tile kt+3 under the tensor work
        int ktn = kt + NSTAGES - 1;
        uint32_t sb = smem_base + ld_stage * STAGE_BYTES;
        if (ktn < KTILES) {
            int kof = ktn * BK;
#pragma unroll
            for (int i = 0; i < 4; ++i) cp_async16(sb + a_soff[i], a_gp[i] + kof);
        }

        // ks1
        {
            uint32_t k32 = 32;
#pragma unroll
            for (int im = 0; im < 4; ++im)
                ldmatrix_x4(a[im][0], a[im][1], a[im][2], a[im][3],
                            sS + a_row[im] + ((k32 + a_khb) ^ a_xor[im]));
#pragma unroll
            for (int jp = 0; jp < 4; ++jp)
                ldmatrix_x4(b[2 * jp][0], b[2 * jp][1],
                            b[2 * jp + 1][0], b[2 * jp + 1][1],
                            sS + b_row[jp] + ((k32 + b_khb) ^ b_xor[jp]));
#pragma unroll
            for (int im = 0; im < 4; ++im)
#pragma unroll
                for (int jn = 0; jn < 8; ++jn)
                    mma_16816(acc[im][jn][0], acc[im][jn][1],
                              acc[im][jn][2], acc[im][jn][3],
                              a[im][0], a[im][1], a[im][2], a[im][3],
                              b[jn][0], b[jn][1]);
        }

        // B copies for tile kt+3, then commit the group
        if (ktn < KTILES) {
            int kof = ktn * BK;
#pragma unroll
            for (int i = 0; i < 8; ++i) cp_async16(sb + b_soff[i], b_gp[i] + kof);
        }
        asm volatile("cp.async.commit_group;");

        // ks2..ks3
#pragma unroll
        for (int ks = 2; ks < 4; ++ks) {
            uint32_t k32 = (uint32_t)(ks * 32);
#pragma unroll
            for (int im = 0; im < 4; ++im)
                ldmatrix_x4(a[im][0], a[im][1], a[im][2], a[im][3],
                            sS + a_row[im] + ((k32 + a_khb) ^ a_xor[im]));
#pragma unroll
            for (int jp = 0; jp < 4; ++jp)
                ldmatrix_x4(b[2 * jp][0], b[2 * jp][1],
                            b[2 * jp + 1][0], b[2 * jp + 1][1],
                            sS + b_row[jp] + ((k32 + b_khb) ^ b_xor[jp]));
#pragma unroll
            for (int im = 0; im < 4; ++im)
#pragma unroll
                for (int jn = 0; jn < 8; ++jn)
                    mma_16816(acc[im][jn][0], acc[im][jn][1],
                              acc[im][jn][2], acc[im][jn][3],
                              a[im][0], a[im][1], a[im][2], a[im][3],
                              b[jn][0], b[jn][1]);
        }

        // tail rendezvous: tile kt+1's copies complete, publish for all
        asm volatile("cp.async.wait_group %0;" :: "n"(NSTAGES - 2));
        __syncthreads();

        // cross-tile prefetch: ks0 frags of tile kt+1
        if (kt + 1 < KTILES) {
            int ns = (cp_stage == NSTAGES - 1) ? 0 : cp_stage + 1;
            uint32_t sN = smem_base + ns * STAGE_BYTES;
#pragma unroll
            for (int im = 0; im < 4; ++im)
                ldmatrix_x4(a[im][0], a[im][1], a[im][2], a[im][3],
                            sN + a_row[im] + (a_khb ^ a_xor[im]));
#pragma unroll
            for (int jp = 0; jp < 4; ++jp)
                ldmatrix_x4(b[2 * jp][0], b[2 * jp][1],
                            b[2 * jp + 1][0], b[2 * jp + 1][1],
                            sN + b_row[jp] + (b_khb ^ b_xor[jp]));
        }

        ld_stage = (ld_stage == NSTAGES - 1) ? 0 : ld_stage + 1;
        cp_stage = (cp_stage == NSTAGES - 1) ? 0 : cp_stage + 1;
    }

    // ---- epilogue: bias + store ----
#pragma unroll
    for (int im = 0; im < 4; ++im) {
        int r0 = m0 + warp_m * 64 + im * 16 + (lane >> 2);
        int r1 = r0 + 8;
#pragma unroll
        for (int jn = 0; jn < 8; ++jn) {
            int c = n0 + warp_n * 64 + jn * 8 + (lane & 3) * 2;
            float2 bv = *reinterpret_cast<const float2*>(bias + c);
            float2 o0, o1;
            o0.x = acc[im][jn][0] + bv.x;
            o0.y = acc[im][jn][1] + bv.y;
            o1.x = acc[im][jn][2] + bv.x;
            o1.y = acc[im][jn][3] + bv.y;
            *reinterpret_cast<float2*>(out + (size_t)r0 * OUT_F + c) = o0;
            *reinterpret_cast<float2*>(out + (size_t)r1 * OUT_F + c) = o1;
        }
    }
}

// ============================================================
// Host launcher
// ============================================================
extern "C" void kernel_launch(void* const* d_in, const int* in_sizes, int n_in,
                              void* d_out, int out_size) {
    const float* x      = (const float*)d_in[0];
    const float* w_twos = (const float*)d_in[1];
    const float* b      = (const float*)d_in[2];
    const float* base   = (const float*)d_in[3];
    float* out = (float*)d_out;

    cudaFuncSetAttribute(gemm_kernel,
                         cudaFuncAttributeMaxDynamicSharedMemorySize, SMEM_TOTAL);

    prep_kernel<<<WBLOCKS + XBLOCKS, 256>>>(x, w_twos, base);

    dim3 grid(OUT_F / BN, N_TOK / BM);
    gemm_kernel<<<grid, GTHREADS, SMEM_TOTAL>>>(b, out);
}

// round 10
// speedup vs baseline: 1.1780x; 1.0556x over previous
#include <cuda_runtime.h>
#include <cuda_fp16.h>
#include <cstdint>
#include <cstddef>

// ============================================================
// Problem constants
// ============================================================
#define N_TOK 8192
#define OUT_F 4096
#define IN_F  4096
#define NBITS 8
#define STEPF 0.0078125f

// GEMM tiling: 1 CTA/SM, 64x64 warp tile, BK=128, 2-stage ring
#define BM 128
#define BN 256
#define BK 128
#define KTILES (IN_F / BK)      // 32
#define GTHREADS 256

// Stage layout (96KB): A sub0 16KB | A sub1 16KB | B sub0 32KB | B sub1 32KB
// Each subtile holds 64 K-columns at 128B/row (keeps swizzle + LDSM addressing).
#define A_SUB_BYTES 16384
#define B_SUB_BYTES 32768
#define OFF_A0 0
#define OFF_A1 16384
#define OFF_B0 32768
#define OFF_B1 65536
#define STAGE_BYTES 98304
#define SMEM_TOTAL  (2 * STAGE_BYTES)   // 196608

// ============================================================
// Device scratch (allocation-free rule: __device__ globals)
// ============================================================
__device__ __align__(16) __half g_X[(size_t)N_TOK * IN_F];   // 64 MB
__device__ __align__(16) __half g_W[(size_t)OUT_F * IN_F];   // 32 MB

// ============================================================
// Helpers
// ============================================================
__device__ __forceinline__ uint32_t smem_u32(const void* p) {
    uint32_t a;
    asm("{ .reg .u64 t; cvta.to.shared.u64 t, %1; cvt.u32.u64 %0, t; }"
        : "=r"(a) : "l"(p));
    return a;
}

__device__ __forceinline__ void cp_async16(uint32_t saddr, const void* gaddr) {
    asm volatile("cp.async.cg.shared.global [%0], [%1], 16;"
                 :: "r"(saddr), "l"(gaddr));
}

__device__ __forceinline__ void ldmatrix_x4(uint32_t& r0, uint32_t& r1,
                                            uint32_t& r2, uint32_t& r3,
                                            uint32_t addr) {
    asm volatile("ldmatrix.sync.aligned.m8n8.x4.shared.b16 {%0,%1,%2,%3}, [%4];"
                 : "=r"(r0), "=r"(r1), "=r"(r2), "=r"(r3) : "r"(addr));
}

__device__ __forceinline__ void mma_16816(float& d0, float& d1, float& d2, float& d3,
                                          uint32_t a0, uint32_t a1, uint32_t a2, uint32_t a3,
                                          uint32_t b0, uint32_t b1) {
    asm volatile(
        "mma.sync.aligned.m16n8k16.row.col.f32.f16.f16.f32 "
        "{%0,%1,%2,%3}, {%4,%5,%6,%7}, {%8,%9}, {%0,%1,%2,%3};"
        : "+f"(d0), "+f"(d1), "+f"(d2), "+f"(d3)
        : "r"(a0), "r"(a1), "r"(a2), "r"(a3), "r"(b0), "r"(b1));
}

// ============================================================
// Fused prep kernel (measured at HBM roofline — unchanged)
// ============================================================
#define WBLOCKS 32768   // (OUT_F*IN_F/2) / 256
#define XBLOCKS 32768   // (N_TOK*IN_F/4) / 256

__global__ void prep_kernel(const float* __restrict__ x,
                            const float* __restrict__ w_twos,
                            const float* __restrict__ base) {
    if (blockIdx.x < WBLOCKS) {
        size_t p = (size_t)blockIdx.x * blockDim.x + threadIdx.x;

        float bs[NBITS];
#pragma unroll
        for (int j = 0; j < NBITS; j++) bs[j] = __ldg(base + j);

        const float4* src = reinterpret_cast<const float4*>(w_twos + p * 2 * NBITS);
        float4 a0 = src[0], a1 = src[1], a2 = src[2], a3 = src[3];

        float w0 = a0.x * bs[0] + a0.y * bs[1] + a0.z * bs[2] + a0.w * bs[3] +
                   a1.x * bs[4] + a1.y * bs[5] + a1.z * bs[6] + a1.w * bs[7];
        float w1 = a2.x * bs[0] + a2.y * bs[1] + a2.z * bs[2] + a2.w * bs[3] +
                   a3.x * bs[4] + a3.y * bs[5] + a3.z * bs[6] + a3.w * bs[7];

        __half2 h = __floats2half2_rn(w0 * STEPF, w1 * STEPF);
        reinterpret_cast<uint32_t*>(g_W)[p] = *reinterpret_cast<uint32_t*>(&h);
    } else {
        size_t i = (size_t)(blockIdx.x - WBLOCKS) * blockDim.x + threadIdx.x;
        float4 v = reinterpret_cast<const float4*>(x)[i];
        __half2 h01 = __floats2half2_rn(v.x, v.y);
        __half2 h23 = __floats2half2_rn(v.z, v.w);
        uint2 pk;
        pk.x = *reinterpret_cast<uint32_t*>(&h01);
        pk.y = *reinterpret_cast<uint32_t*>(&h23);
        reinterpret_cast<uint2*>(g_X)[i] = pk;
    }
}

// ============================================================
// fp16 mma.sync GEMM  out[m,n] = sum_k X[m,k]*W[n,k] + b[n]
// BM=128, BN=256, BK=128, 8 warps (2m x 4n, warp tile 64x64),
// 2-stage ring (96KB each), barrier every 8 ks steps,
// drip-fed cp.async, cross-tile ks0 prefetch.
// ============================================================
__global__ __launch_bounds__(GTHREADS, 1)
void gemm_kernel(const float* __restrict__ bias, float* __restrict__ out) {
    extern __shared__ char sm[];
    const uint32_t smem_base = smem_u32(sm);
    const int tid  = threadIdx.x;
    const int wid  = tid >> 5;
    const int lane = tid & 31;
    const int warp_m = wid & 1;    // 64 rows each
    const int warp_n = wid >> 1;   // 0..3, 64 cols each
    const int m0 = blockIdx.y * BM;
    const int n0 = blockIdx.x * BN;

    // ---- per-lane ldmatrix addressing (within a 64-col subtile) ----
    uint32_t a_row[4], a_xor[4];
#pragma unroll
    for (int im = 0; im < 4; ++im) {
        int r = warp_m * 64 + im * 16 + (lane & 15);
        a_row[im] = (uint32_t)(r * 128);
        a_xor[im] = (uint32_t)((r & 7) * 16);
    }
    const uint32_t a_khb = (uint32_t)((lane >> 4) * 16);

    uint32_t b_row[4], b_xor[4];
#pragma unroll
    for (int jp = 0; jp < 4; ++jp) {
        int r = warp_n * 64 + jp * 16 + ((lane >> 4) * 8) + (lane & 7);
        b_row[jp] = (uint32_t)(r * 128);
        b_xor[jp] = (uint32_t)((r & 7) * 16);
    }
    const uint32_t b_khb = (uint32_t)(((lane >> 3) & 1) * 16);

    // ---- cp.async lane assignments (per 64-col subtile) ----
    // A subtile: 1024 16B chunks (4/thr); B subtile: 2048 (8/thr)
    uint32_t a_soff[4];  const __half* a_gp[4];
    uint32_t b_soff[8];  const __half* b_gp[8];
#pragma unroll
    for (int i = 0; i < 4; ++i) {
        int id = tid + i * 256;
        int r = id >> 3, c = id & 7;
        a_soff[i] = (uint32_t)(r * 128 + ((c * 16) ^ ((r & 7) * 16)));
        a_gp[i] = g_X + (size_t)(m0 + r) * IN_F + c * 8;
    }
#pragma unroll
    for (int i = 0; i < 8; ++i) {
        int id = tid + i * 256;
        int r = id >> 3, c = id & 7;
        b_soff[i] = (uint32_t)(r * 128 + ((c * 16) ^ ((r & 7) * 16)));
        b_gp[i] = g_W + (size_t)(n0 + r) * IN_F + c * 8;
    }

    float acc[4][8][4];   // 128 regs: warp tile 64x64
#pragma unroll
    for (int im = 0; im < 4; ++im)
#pragma unroll
        for (int jn = 0; jn < 8; ++jn)
#pragma unroll
            for (int q = 0; q < 4; ++q) acc[im][jn][q] = 0.0f;

    // ---- prologue: load tile 0 into stage 0 ----
    {
        uint32_t sb = smem_base;
#pragma unroll
        for (int i = 0; i < 4; ++i) {
            cp_async16(sb + OFF_A0 + a_soff[i], a_gp[i]);
            cp_async16(sb + OFF_A1 + a_soff[i], a_gp[i] + 64);
        }
#pragma unroll
        for (int i = 0; i < 8; ++i) {
            cp_async16(sb + OFF_B0 + b_soff[i], b_gp[i]);
            cp_async16(sb + OFF_B1 + b_soff[i], b_gp[i] + 64);
        }
        asm volatile("cp.async.commit_group;");
    }
    asm volatile("cp.async.wait_group 0;");
    __syncthreads();

    uint32_t a[4][4];   // single-buffer fragments
    uint32_t b[8][2];

    // prefetch ks0 frags of tile 0
    {
        uint32_t sS = smem_base;
#pragma unroll
        for (int im = 0; im < 4; ++im)
            ldmatrix_x4(a[im][0], a[im][1], a[im][2], a[im][3],
                        sS + OFF_A0 + a_row[im] + (a_khb ^ a_xor[im]));
#pragma unroll
        for (int jp = 0; jp < 4; ++jp)
            ldmatrix_x4(b[2 * jp][0], b[2 * jp][1],
                        b[2 * jp + 1][0], b[2 * jp + 1][1],
                        sS + OFF_B0 + b_row[jp] + (b_khb ^ b_xor[jp]));
    }

    // ---- main loop: 32 K-tiles, barrier only at tile tail ----
    for (int kt = 0; kt < KTILES; ++kt) {
        const uint32_t sS = smem_base + (kt & 1) * STAGE_BYTES;
        const uint32_t sb = smem_base + ((kt + 1) & 1) * STAGE_BYTES;
        const int ktn = kt + 1;
        const int kof = ktn * BK;

#pragma unroll
        for (int ks = 0; ks < 8; ++ks) {
            // frag loads for this ks (ks0 was prefetched across the barrier)
            if (ks > 0) {
                const uint32_t aoff = (ks & 4) ? OFF_A1 : OFF_A0;
                const uint32_t boff = (ks & 4) ? OFF_B1 : OFF_B0;
                const uint32_t k32 = (uint32_t)((ks & 3) * 32);
#pragma unroll
                for (int im = 0; im < 4; ++im)
                    ldmatrix_x4(a[im][0], a[im][1], a[im][2], a[im][3],
                                sS + aoff + a_row[im] + ((k32 + a_khb) ^ a_xor[im]));
#pragma unroll
                for (int jp = 0; jp < 4; ++jp)
                    ldmatrix_x4(b[2 * jp][0], b[2 * jp][1],
                                b[2 * jp + 1][0], b[2 * jp + 1][1],
                                sS + boff + b_row[jp] + ((k32 + b_khb) ^ b_xor[jp]));
            }
#pragma unroll
            for (int im = 0; im < 4; ++im)
#pragma unroll
                for (int jn = 0; jn < 8; ++jn)
                    mma_16816(acc[im][jn][0], acc[im][jn][1],
                              acc[im][jn][2], acc[im][jn][3],
                              a[im][0], a[im][1], a[im][2], a[im][3],
                              b[jn][0], b[jn][1]);

            // drip-feed next tile's copies under the tensor work
            if (ktn < KTILES) {
                if (ks == 0) {
#pragma unroll
                    for (int i = 0; i < 4; ++i)
                        cp_async16(sb + OFF_A0 + a_soff[i], a_gp[i] + kof);
                } else if (ks == 1) {
#pragma unroll
                    for (int i = 0; i < 8; ++i)
                        cp_async16(sb + OFF_B0 + b_soff[i], b_gp[i] + kof);
                } else if (ks == 2) {
#pragma unroll
                    for (int i = 0; i < 4; ++i)
                        cp_async16(sb + OFF_A1 + a_soff[i], a_gp[i] + kof + 64);
                } else if (ks == 3) {
#pragma unroll
                    for (int i = 0; i < 8; ++i)
                        cp_async16(sb + OFF_B1 + b_soff[i], b_gp[i] + kof + 64);
                    asm volatile("cp.async.commit_group;");
                }
            }
        }

        // tail rendezvous: next tile's copies complete, publish, flip stages
        asm volatile("cp.async.wait_group 0;");
        __syncthreads();

        // cross-tile prefetch: ks0 frags of tile kt+1 from the other stage
        if (ktn < KTILES) {
#pragma unroll
            for (int im = 0; im < 4; ++im)
                ldmatrix_x4(a[im][0], a[im][1], a[im][2], a[im][3],
                            sb + OFF_A0 + a_row[im] + (a_khb ^ a_xor[im]));
#pragma unroll
            for (int jp = 0; jp < 4; ++jp)
                ldmatrix_x4(b[2 * jp][0], b[2 * jp][1],
                            b[2 * jp + 1][0], b[2 * jp + 1][1],
                            sb + OFF_B0 + b_row[jp] + (b_khb ^ b_xor[jp]));
        }
    }

    // ---- epilogue: bias + store ----
#pragma unroll
    for (int im = 0; im < 4; ++im) {
        int r0 = m0 + warp_m * 64 + im * 16 + (lane >> 2);
        int r1 = r0 + 8;
#pragma unroll
        for (int jn = 0; jn < 8; ++jn) {
            int c = n0 + warp_n * 64 + jn * 8 + (lane & 3) * 2;
            float2 bv = *reinterpret_cast<const float2*>(bias + c);
            float2 o0, o1;
            o0.x = acc[im][jn][0] + bv.x;
            o0.y = acc[im][jn][1] + bv.y;
            o1.x = acc[im][jn][2] + bv.x;
            o1.y = acc[im][jn][3] + bv.y;
            *reinterpret_cast<float2*>(out + (size_t)r0 * OUT_F + c) = o0;
            *reinterpret_cast<float2*>(out + (size_t)r1 * OUT_F + c) = o1;
        }
    }
}

// ============================================================
// Host launcher
// ============================================================
extern "C" void kernel_launch(void* const* d_in, const int* in_sizes, int n_in,
                              void* d_out, int out_size) {
    const float* x      = (const float*)d_in[0];
    const float* w_twos = (const float*)d_in[1];
    const float* b      = (const float*)d_in[2];
    const float* base   = (const float*)d_in[3];
    float* out = (float*)d_out;

    cudaFuncSetAttribute(gemm_kernel,
                         cudaFuncAttributeMaxDynamicSharedMemorySize, SMEM_TOTAL);

    prep_kernel<<<WBLOCKS + XBLOCKS, 256>>>(x, w_twos, base);

    dim3 grid(OUT_F / BN, N_TOK / BM);
    gemm_kernel<<<grid, GTHREADS, SMEM_TOTAL>>>(b, out);
}